// round 6
// baseline (speedup 1.0000x reference)
#include <cuda_runtime.h>

// LSTM_60808146977081: B=4096, T=512, I=10, H=32, fp32.
// TWO batch elements per warp (weights register-shared across the pair) ->
// halves total register-file demand -> waves 3.46 -> 1.73, doubles per-warp
// ILP (8 independent FFMA2 chains). lane = hidden unit.
// Gate math via packed fma.rn.f32x2 (sm_103a FFMA2).

#define FULL_MASK 0xFFFFFFFFu

__device__ __forceinline__ float2 ffma2(float2 a, float2 b, float2 c) {
    union F2U { float2 f; unsigned long long u; };
    F2U ua, ub, uc, ud;
    ua.f = a; ub.f = b; uc.f = c;
    asm("fma.rn.f32x2 %0, %1, %2, %3;"
        : "=l"(ud.u) : "l"(ua.u), "l"(ub.u), "l"(uc.u));
    return ud.f;
}

__device__ __forceinline__ float sigmoid_fast(float x) {
    // exp(-x) -> +inf for very negative x -> 1/(1+inf) = 0. Safe.
    return __fdividef(1.0f, 1.0f + __expf(-x));
}

__device__ __forceinline__ float tanh_fast(float x) {
    // tanh(|x|) = (1 - e^{-2|x|}) / (1 + e^{-2|x|}), e in (0,1] -> no overflow.
    float e = __expf(-2.0f * fabsf(x));
    float r = __fdividef(1.0f - e, 1.0f + e);
    return copysignf(r, x);
}

__global__ void __launch_bounds__(128, 2)
lstm_warp_pair(const float* __restrict__ x,
               const float* __restrict__ h0,
               const float* __restrict__ c0,
               const float* __restrict__ W_ih,
               const float* __restrict__ W_hh,
               const float* __restrict__ b_ih,
               const float* __restrict__ b_hh,
               const float* __restrict__ W_lin,
               const float* __restrict__ b_lin,
               float* __restrict__ out)
{
    constexpr int T = 512;
    constexpr int I = 10;

    const int warp = threadIdx.x >> 5;
    const int lane = threadIdx.x & 31;
    const int b0   = (blockIdx.x * 4 + warp) * 2;   // pair of batches
    const int b1   = b0 + 1;

    // per-warp h broadcast: [buf][pair][lane], double-buffered -> 1 syncwarp/step
    __shared__ float sh[4][2][2][32];

    // ---- Weights -> registers (SHARED across the batch pair) ----
    float2 wh[4][16];   // W_hh rows (gate g*32+lane), pairs along j
    float2 wi[4][5];    // W_ih rows, pairs along i
    float  bias[4];
#pragma unroll
    for (int g = 0; g < 4; g++) {
        const int r = g * 32 + lane;
        const float2* whp = reinterpret_cast<const float2*>(W_hh + r * 32);
#pragma unroll
        for (int p = 0; p < 16; p++) wh[g][p] = whp[p];
        const float2* wip = reinterpret_cast<const float2*>(W_ih + r * I);
#pragma unroll
        for (int q = 0; q < 5; q++) wi[g][q] = wip[q];
        bias[g] = b_ih[r] + b_hh[r];
    }
    const float wl = W_lin[lane];

    float h[2], c[2];
    h[0] = h0[b0 * 32 + lane];  c[0] = c0[b0 * 32 + lane];
    h[1] = h0[b1 * 32 + lane];  c[1] = c0[b1 * 32 + lane];

    const float2* xw0 = reinterpret_cast<const float2*>(x + (size_t)b0 * (T * I));
    const float2* xw1 = reinterpret_cast<const float2*>(x + (size_t)b1 * (T * I));

    for (int t = 0; t < T; t++) {
        const int buf = t & 1;
        sh[warp][buf][0][lane] = h[0];
        sh[warp][buf][1][lane] = h[1];
        __syncwarp();

        // x_t for both batches (L1-resident stream, hidden behind FMA chains)
        float2 xc0[5], xc1[5];
        const float2* p0 = xw0 + (size_t)t * 5;
        const float2* p1 = xw1 + (size_t)t * 5;
#pragma unroll
        for (int q = 0; q < 5; q++) { xc0[q] = p0[q]; xc1[q] = p1[q]; }

        float2 acc[2][4];
#pragma unroll
        for (int g = 0; g < 4; g++) {
            acc[0][g] = make_float2(bias[g], 0.0f);
            acc[1][g] = make_float2(bias[g], 0.0f);
        }

        // Recurrent matvec for both batches: 8 independent FFMA2 chains
        const float4* hA = reinterpret_cast<const float4*>(sh[warp][buf][0]);
        const float4* hB = reinterpret_cast<const float4*>(sh[warp][buf][1]);
#pragma unroll
        for (int p = 0; p < 8; p++) {
            const float4 a4 = hA[p];
            const float4 b4 = hB[p];
            const float2 aLo = make_float2(a4.x, a4.y);
            const float2 aHi = make_float2(a4.z, a4.w);
            const float2 bLo = make_float2(b4.x, b4.y);
            const float2 bHi = make_float2(b4.z, b4.w);
#pragma unroll
            for (int g = 0; g < 4; g++) {
                acc[0][g] = ffma2(wh[g][2 * p],     aLo, acc[0][g]);
                acc[0][g] = ffma2(wh[g][2 * p + 1], aHi, acc[0][g]);
                acc[1][g] = ffma2(wh[g][2 * p],     bLo, acc[1][g]);
                acc[1][g] = ffma2(wh[g][2 * p + 1], bHi, acc[1][g]);
            }
        }
        // Input matvec
#pragma unroll
        for (int q = 0; q < 5; q++) {
#pragma unroll
            for (int g = 0; g < 4; g++) {
                acc[0][g] = ffma2(wi[g][q], xc0[q], acc[0][g]);
                acc[1][g] = ffma2(wi[g][q], xc1[q], acc[1][g]);
            }
        }

        // Activations + state update, both batches (independent chains)
#pragma unroll
        for (int pr = 0; pr < 2; pr++) {
            const float gi = acc[pr][0].x + acc[pr][0].y;
            const float gf = acc[pr][1].x + acc[pr][1].y;
            const float gg = acc[pr][2].x + acc[pr][2].y;
            const float go = acc[pr][3].x + acc[pr][3].y;

            const float ig = sigmoid_fast(gi);
            const float fg = sigmoid_fast(gf);
            const float gc = tanh_fast(gg);
            const float og = sigmoid_fast(go);

            c[pr] = fg * c[pr] + ig * gc;
            h[pr] = og * tanh_fast(c[pr]);
        }
    }

    // out[b] = sum_k h[k] * W_lin[0,k] + b_lin   (both batches)
    float v0 = h[0] * wl;
    float v1 = h[1] * wl;
#pragma unroll
    for (int off = 16; off; off >>= 1) {
        v0 += __shfl_xor_sync(FULL_MASK, v0, off);
        v1 += __shfl_xor_sync(FULL_MASK, v1, off);
    }
    if (lane == 0) {
        out[b0] = v0 + b_lin[0];
        out[b1] = v1 + b_lin[0];
    }
}

extern "C" void kernel_launch(void* const* d_in, const int* in_sizes, int n_in,
                              void* d_out, int out_size)
{
    const float* x     = (const float*)d_in[0];
    const float* h0    = (const float*)d_in[1];
    const float* c0    = (const float*)d_in[2];
    const float* W_ih  = (const float*)d_in[3];
    const float* W_hh  = (const float*)d_in[4];
    const float* b_ih  = (const float*)d_in[5];
    const float* b_hh  = (const float*)d_in[6];
    const float* W_lin = (const float*)d_in[7];
    const float* b_lin = (const float*)d_in[8];
    float* out = (float*)d_out;

    // 4096 batches, 2 per warp, 4 warps per 128-thread block -> 512 blocks
    lstm_warp_pair<<<512, 128>>>(x, h0, c0, W_ih, W_hh, b_ih, b_hh,
                                 W_lin, b_lin, out);
}